// round 4
// baseline (speedup 1.0000x reference)
#include <cuda_runtime.h>

// Fused 3D windowed attention block — FFMA2 with pre-packed SMEM layouts.
// One CTA per 4x4x4 window (4096 CTAs, 256 threads).
//
// SMEM regions (float offsets):
//   xs2 [64][258]   dup input: (v,v) pairs along k           (dead after QKV)
//   qs  [64][388]   Q[0:128) K[128:256) V[256:384)           (dead after attn)
//   wt2 [128][130]  col-pair weight tile; reused as yP after QKV
//   cwd [128][258]  dup conv weights, overlaid on xs2+qs after attention

#define D0 30
#define H0 62
#define W0 126
#define MTOT (30*62*126)

#define DUP_STRIDE 258
#define PAIR_STRIDE 130
#define QS_STRIDE 388

#define XS_OFF 0
#define QS_OFF 16512
#define WT_OFF (16512 + 24832)            // 41344
#define SMEM_FLOATS (WT_OFF + 16640)      // 57984 floats = 231936 B

typedef unsigned long long u64;

__device__ __forceinline__ u64 pack2(float a, float b) {
    u64 d;
    asm("mov.b64 %0, {%1, %2};" : "=l"(d) : "r"(__float_as_uint(a)), "r"(__float_as_uint(b)));
    return d;
}
__device__ __forceinline__ void unpack2(u64 v, float& a, float& b) {
    unsigned x, y;
    asm("mov.b64 {%0, %1}, %2;" : "=r"(x), "=r"(y) : "l"(v));
    a = __uint_as_float(x);
    b = __uint_as_float(y);
}
__device__ __forceinline__ u64 ffma2(u64 a, u64 b, u64 c) {
    u64 d;
    asm("fma.rn.f32x2 %0, %1, %2, %3;" : "=l"(d) : "l"(a), "l"(b), "l"(c));
    return d;
}
__device__ __forceinline__ u64 add2(u64 a, u64 b) {
    u64 d;
    asm("add.rn.f32x2 %0, %1, %2;" : "=l"(d) : "l"(a), "l"(b));
    return d;
}
__device__ __forceinline__ float dot4(float4 a, float4 b) {
    return fmaf(a.x, b.x, fmaf(a.y, b.y, fmaf(a.z, b.z, a.w * b.w)));
}

// Column-pair weight tile: Ws[k*130 + o] = W[o][k]. Bank-rotated scatter (2-way STS).
__device__ __forceinline__ void load_wpair(const float* __restrict__ W,
                                           float* __restrict__ Ws, int t) {
    const int lane = t & 31, w = t >> 5;
    const int rot = lane >> 2;
    #pragma unroll
    for (int it = 0; it < 16; ++it) {
        int o = w + 8 * it;
        float4 v = *(const float4*)(W + o * 128 + 4 * lane);
        float vv[4] = {v.x, v.y, v.z, v.w};
        #pragma unroll
        for (int s = 0; s < 4; ++s) {
            int sp = (s + rot) & 3;
            Ws[(4 * lane + sp) * PAIR_STRIDE + o] = vv[sp];
        }
    }
}

// Duplicated weight tile: Wd[o*258 + 2k..2k+1] = (W[o][k], W[o][k]).
__device__ __forceinline__ void load_wdup(const float* __restrict__ W,
                                          float* __restrict__ Wd, int t) {
    const int lane = t & 31, w = t >> 5;
    #pragma unroll
    for (int it = 0; it < 16; ++it) {
        int o = w + 8 * it;
        float4 v = *(const float4*)(W + o * 128 + 4 * lane);
        u64* dst = (u64*)(Wd + o * DUP_STRIDE + 8 * lane);
        dst[0] = pack2(v.x, v.x);
        dst[1] = pack2(v.y, v.y);
        dst[2] = pack2(v.z, v.z);
        dst[3] = pack2(v.w, v.w);
    }
}

// QKV GEMM: 64 voxel rows x 128 out cols x 128 k.
// rows: ty+16i (i<4); col pairs (2j,2j+1), j = tx+16p (p<4). Zero runtime packs.
__device__ __forceinline__ void gemm_qkv(const float* __restrict__ Ad,
                                         const float* __restrict__ Bp,
                                         int tx, int ty, u64 acc[4][4]) {
    #pragma unroll 4
    for (int k = 0; k < 128; ++k) {
        u64 b[4], a[4];
        #pragma unroll
        for (int p = 0; p < 4; ++p)
            b[p] = *(const u64*)(Bp + k * PAIR_STRIDE + 2 * (tx + 16 * p));
        #pragma unroll
        for (int i = 0; i < 4; ++i)
            a[i] = *(const u64*)(Ad + (ty + 16 * i) * DUP_STRIDE + 2 * k);
        #pragma unroll
        for (int i = 0; i < 4; ++i)
            #pragma unroll
            for (int p = 0; p < 4; ++p)
                acc[i][p] = ffma2(a[i], b[p], acc[i][p]);
    }
}

// Conv GEMM: 128 channel rows x 64 voxel cols x 128 k (channels).
// rows: o = ty+16i (i<8); voxel pairs (2j,2j+1), j = tx+16p (p<2).
__device__ __forceinline__ void gemm_conv(const float* __restrict__ Wd,
                                          const float* __restrict__ Yp,
                                          int tx, int ty, u64 acc[8][2]) {
    #pragma unroll 4
    for (int c = 0; c < 128; ++c) {
        u64 b[2], a[8];
        #pragma unroll
        for (int p = 0; p < 2; ++p)
            b[p] = *(const u64*)(Yp + c * PAIR_STRIDE + 2 * (tx + 16 * p));
        #pragma unroll
        for (int i = 0; i < 8; ++i)
            a[i] = *(const u64*)(Wd + (ty + 16 * i) * DUP_STRIDE + 2 * c);
        #pragma unroll
        for (int i = 0; i < 8; ++i)
            #pragma unroll
            for (int p = 0; p < 2; ++p)
                acc[i][p] = ffma2(a[i], b[p], acc[i][p]);
    }
}

__global__ void __launch_bounds__(256, 1)
fused_window_attn_kernel(const float* __restrict__ x,
                         const float* __restrict__ qkv_w,
                         const float* __restrict__ qkv_b,
                         const float* __restrict__ conv_w,
                         const float* __restrict__ conv_b,
                         float* __restrict__ out)
{
    extern __shared__ float sm[];
    float* xs2 = sm + XS_OFF;
    float* qs  = sm + QS_OFF;
    float* wt2 = sm + WT_OFF;   // pair weights during QKV, yP after
    float* cwd = sm;            // conv dup weights after attention (xs2+qs dead)

    const int t  = threadIdx.x;
    const int wi = blockIdx.x;
    const int bz = wi >> 9;
    const int by = (wi >> 5) & 15;
    const int bx = wi & 31;
    const int z0 = bz * 4, y0 = by * 4, x0 = bx * 4;

    // ---------------- phase 1: gather window (dup layout) + chunk0 weights ----
    #pragma unroll 4
    for (int idx = t; idx < 64 * 128; idx += 256) {
        int l = idx & 63;
        int c = idx >> 6;
        int gz = z0 + (l >> 4);
        int gy = y0 + ((l >> 2) & 3);
        int gx = x0 + (l & 3);
        float v = 0.f;
        if (gz < D0 && gy < H0 && gx < W0)
            v = x[((c * D0 + gz) * H0 + gy) * W0 + gx];
        *(u64*)(xs2 + l * DUP_STRIDE + 2 * c) = pack2(v, v);
    }
    load_wpair(qkv_w, wt2, t);

    const int tx = t & 15;
    const int ty = t >> 4;

    // ---------------- phase 2: QKV GEMM, 3 chunks ----------------
    #pragma unroll 1
    for (int chunk = 0; chunk < 3; ++chunk) {
        if (chunk > 0) {
            __syncthreads();
            load_wpair(qkv_w + chunk * 128 * 128, wt2, t);
        }
        __syncthreads();

        u64 acc[4][4];
        #pragma unroll
        for (int i = 0; i < 4; ++i)
            #pragma unroll
            for (int p = 0; p < 4; ++p) acc[i][p] = 0ull;

        gemm_qkv(xs2, wt2, tx, ty, acc);

        #pragma unroll
        for (int i = 0; i < 4; ++i) {
            int row = ty + 16 * i;
            #pragma unroll
            for (int p = 0; p < 4; ++p) {
                int j = tx + 16 * p;
                u64 bias = *(const u64*)(qkv_b + chunk * 128 + 2 * j);
                *(u64*)(qs + row * QS_STRIDE + chunk * 128 + 2 * j) =
                    add2(acc[i][p], bias);
            }
        }
    }
    __syncthreads();

    // ---------------- phase 3: attention ----------------
    unsigned long long pm = 0ull;
    if (bz == 7 || by == 15 || bx == 31) {
        #pragma unroll
        for (int m = 0; m < 64; ++m) {
            bool p = (bz == 7 && (m >> 4) >= 2) ||
                     (by == 15 && ((m >> 2) & 3) >= 2) ||
                     (bx == 31 && (m & 3) >= 2);
            pm |= (unsigned long long)(p ? 1u : 0u) << m;
        }
    }

    const int head = t >> 5;
    const int lane = t & 31;
    const int r0 = lane, r1 = lane + 32;
    const unsigned p0 = (unsigned)(pm >> r0) & 1u;
    const unsigned p1 = (unsigned)(pm >> r1) & 1u;

    float4 q0[4], q1[4];
    {
        const float4* q0p = (const float4*)(qs + r0 * QS_STRIDE + head * 16);
        const float4* q1p = (const float4*)(qs + r1 * QS_STRIDE + head * 16);
        #pragma unroll
        for (int i = 0; i < 4; ++i) { q0[i] = q0p[i]; q1[i] = q1p[i]; }
    }

    u64 acc0[8], acc1[8];
    #pragma unroll
    for (int j = 0; j < 8; ++j) { acc0[j] = 0ull; acc1[j] = 0ull; }
    float sum0 = 0.f, sum1 = 0.f;

    const float* kbase = qs + 128 + head * 16;
    const float* vbase = qs + 256 + head * 16;

    #pragma unroll 2
    for (int m = 0; m < 64; ++m) {
        const float4* kp = (const float4*)(kbase + m * QS_STRIDE);
        float4 k0 = kp[0], k1 = kp[1], k2 = kp[2], k3 = kp[3];

        float s0 = dot4(q0[0], k0) + dot4(q0[1], k1) + dot4(q0[2], k2) + dot4(q0[3], k3);
        float s1 = dot4(q1[0], k0) + dot4(q1[1], k1) + dot4(q1[2], k2) + dot4(q1[3], k3);

        unsigned pmm = (unsigned)(pm >> m) & 1u;
        float e0 = (pmm == p0) ? __expf(s0 * 0.25f) : 0.f;
        float e1 = (pmm == p1) ? __expf(s1 * 0.25f) : 0.f;
        sum0 += e0;
        sum1 += e1;
        u64 pe0 = pack2(e0, e0);
        u64 pe1 = pack2(e1, e1);

        const ulonglong2* vp = (const ulonglong2*)(vbase + m * QS_STRIDE);
        #pragma unroll
        for (int j = 0; j < 4; ++j) {
            ulonglong2 vv = vp[j];
            acc0[2 * j]     = ffma2(pe0, vv.x, acc0[2 * j]);
            acc0[2 * j + 1] = ffma2(pe0, vv.y, acc0[2 * j + 1]);
            acc1[2 * j]     = ffma2(pe1, vv.x, acc1[2 * j]);
            acc1[2 * j + 1] = ffma2(pe1, vv.y, acc1[2 * j + 1]);
        }
    }

    // write y into voxel-pair layout yP (reuses wt2): yP[c*130 + l] = y[l][c]
    {
        float inv0 = 1.0f / sum0;
        float inv1 = 1.0f / sum1;
        float* yP = wt2;
        #pragma unroll
        for (int j = 0; j < 8; ++j) {
            float f0, f1;
            unpack2(acc0[j], f0, f1);
            yP[(head * 16 + 2 * j)     * PAIR_STRIDE + r0] = f0 * inv0;
            yP[(head * 16 + 2 * j + 1) * PAIR_STRIDE + r0] = f1 * inv0;
            unpack2(acc1[j], f0, f1);
            yP[(head * 16 + 2 * j)     * PAIR_STRIDE + r1] = f0 * inv1;
            yP[(head * 16 + 2 * j + 1) * PAIR_STRIDE + r1] = f1 * inv1;
        }
    }
    __syncthreads();

    // ---------------- conv weights (dup) over dead xs2+qs ----------------
    load_wdup(conv_w, cwd, t);
    __syncthreads();

    // ---------------- phase 4: 1x1 conv GEMM (128 ch x 64 vox) ----------------
    u64 cacc[8][2];
    #pragma unroll
    for (int i = 0; i < 8; ++i)
        #pragma unroll
        for (int p = 0; p < 2; ++p) cacc[i][p] = 0ull;

    gemm_conv(cwd, wt2, tx, ty, cacc);

    #pragma unroll
    for (int p = 0; p < 2; ++p) {
        int j  = tx + 16 * p;
        int l0 = 2 * j;                        // voxel pair (l0, l0+1), adjacent gx
        int gz = z0 + (l0 >> 4);
        int gy = y0 + ((l0 >> 2) & 3);
        int gx = x0 + (l0 & 3);
        if (gz < D0 && gy < H0 && gx < W0) {   // gx even => gx+1 also valid
            size_t vaddr = (size_t)(gz * H0 + gy) * W0 + gx;
            #pragma unroll
            for (int i = 0; i < 8; ++i) {
                int o = ty + 16 * i;
                float bo = __ldg(conv_b + o);
                *(u64*)(out + (size_t)o * MTOT + vaddr) =
                    add2(cacc[i][p], pack2(bo, bo));
            }
        }
    }
}

extern "C" void kernel_launch(void* const* d_in, const int* in_sizes, int n_in,
                              void* d_out, int out_size)
{
    const float* x      = (const float*)d_in[0];
    const float* qkv_w  = (const float*)d_in[1];
    const float* qkv_b  = (const float*)d_in[2];
    const float* conv_w = (const float*)d_in[3];
    const float* conv_b = (const float*)d_in[4];
    float* out = (float*)d_out;

    cudaFuncSetAttribute(fused_window_attn_kernel,
                         cudaFuncAttributeMaxDynamicSharedMemorySize,
                         SMEM_FLOATS * (int)sizeof(float));

    fused_window_attn_kernel<<<4096, 256, SMEM_FLOATS * sizeof(float)>>>(
        x, qkv_w, qkv_b, conv_w, conv_b, out);
}

// round 6
// speedup vs baseline: 2.8961x; 2.8961x over previous
#include <cuda_runtime.h>
#include <cuda_bf16.h>
#include <cstdint>

// Fused 3D windowed attention block — mma.sync bf16 3-split GEMMs + scalar fp32 attention.
// One CTA per 4x4x4 window (4096 CTAs, 256 threads = 8 warps).

#define D0 30
#define H0 62
#define W0 126
#define MTOT (30*62*126)

#define AST 136            // halves per row, A tiles (64 rows)
#define BST 136            // halves per row, B tiles (128 rows)
#define QS_STRIDE 388

// byte offsets in dynamic smem
#define SM_AHI 0
#define SM_ALO (SM_AHI + 64*AST*2)       // 17408
#define SM_BHI (SM_ALO + 64*AST*2)       // 34816
#define SM_BLO (SM_BHI + 128*BST*2)      // 69632
#define SM_QS  (SM_BLO + 128*BST*2)      // 104448 (16B aligned)
#define SMEM_BYTES (SM_QS + 64*QS_STRIDE*4)   // 203776

__device__ __forceinline__ uint32_t smem_u32(const void* p) {
    uint32_t a;
    asm("{ .reg .u64 t; cvta.to.shared.u64 t, %1; cvt.u32.u64 %0, t; }"
        : "=r"(a) : "l"(p));
    return a;
}
__device__ __forceinline__ void ldsm4(uint32_t (&r)[4], uint32_t addr) {
    asm volatile("ldmatrix.sync.aligned.m8n8.x4.shared.b16 {%0,%1,%2,%3}, [%4];"
                 : "=r"(r[0]), "=r"(r[1]), "=r"(r[2]), "=r"(r[3]) : "r"(addr));
}
__device__ __forceinline__ void ldsm2(uint32_t (&r)[2], uint32_t addr) {
    asm volatile("ldmatrix.sync.aligned.m8n8.x2.shared.b16 {%0,%1}, [%2];"
                 : "=r"(r[0]), "=r"(r[1]) : "r"(addr));
}
__device__ __forceinline__ void mma16816(float (&d)[4], const uint32_t (&a)[4],
                                         const uint32_t (&b)[2]) {
    asm volatile("mma.sync.aligned.m16n8k16.row.col.f32.bf16.bf16.f32 "
                 "{%0,%1,%2,%3}, {%4,%5,%6,%7}, {%8,%9}, {%0,%1,%2,%3};"
                 : "+f"(d[0]), "+f"(d[1]), "+f"(d[2]), "+f"(d[3])
                 : "r"(a[0]), "r"(a[1]), "r"(a[2]), "r"(a[3]),
                   "r"(b[0]), "r"(b[1]));
}

// store (v0,v1) as bf16 hi parts + bf16 residual lo parts at (row, col..col+1)
__device__ __forceinline__ void split_pair(char* hiB, char* loB, int row, int col,
                                           int stride, float v0, float v1) {
    __nv_bfloat16 h0 = __float2bfloat16(v0);
    __nv_bfloat16 h1 = __float2bfloat16(v1);
    __nv_bfloat16 l0 = __float2bfloat16(v0 - __bfloat162float(h0));
    __nv_bfloat16 l1 = __float2bfloat16(v1 - __bfloat162float(h1));
    int off = (row * stride + col) * 2;
    *(__nv_bfloat162*)(hiB + off) = __halves2bfloat162(h0, h1);
    *(__nv_bfloat162*)(loB + off) = __halves2bfloat162(l0, l1);
}

// load 128x128 row-major f32 weight W[n][k] into hi/lo bf16 tiles (stride BST)
__device__ __forceinline__ void load_wsplit(const float* __restrict__ W,
                                            char* hiB, char* loB, int t) {
    #pragma unroll
    for (int it = 0; it < 32; ++it) {
        int idx = t + 256 * it;     // 0..8191
        int n  = idx >> 6;
        int kp = idx & 63;
        float2 wv = *(const float2*)(W + n * 128 + 2 * kp);
        split_pair(hiB, loB, n, 2 * kp, BST, wv.x, wv.y);
    }
}

// one 64x128x128 GEMM pass (3-split): acc[mt][nt][4] over warp n-slice n0..n0+15
__device__ __forceinline__ void mma_block(uint32_t aHi, uint32_t aLo,
                                          uint32_t bHi, uint32_t bLo,
                                          int lane, int n0, float acc[4][2][4]) {
    const int r8 = lane & 7, g = lane >> 3;
    const uint32_t aoff = (uint32_t)(((r8 + 8 * (g & 1)) * AST + 8 * (g >> 1)) * 2);
    const uint32_t boff = (uint32_t)((((lane & 7) + n0) * BST + 8 * ((lane >> 3) & 1)) * 2);
    #pragma unroll
    for (int kk = 0; kk < 8; ++kk) {
        uint32_t ah[4][4], al[4][4], bh[2][2], bl[2][2];
        #pragma unroll
        for (int mt = 0; mt < 4; ++mt) {
            uint32_t o = aoff + (uint32_t)((mt * 16 * AST + kk * 16) * 2);
            ldsm4(ah[mt], aHi + o);
            ldsm4(al[mt], aLo + o);
        }
        #pragma unroll
        for (int nt = 0; nt < 2; ++nt) {
            uint32_t o = boff + (uint32_t)((nt * 8 * BST + kk * 16) * 2);
            ldsm2(bh[nt], bHi + o);
            ldsm2(bl[nt], bLo + o);
        }
        #pragma unroll
        for (int mt = 0; mt < 4; ++mt)
            #pragma unroll
            for (int nt = 0; nt < 2; ++nt) {
                mma16816(acc[mt][nt], ah[mt], bh[nt]);
                mma16816(acc[mt][nt], ah[mt], bl[nt]);
                mma16816(acc[mt][nt], al[mt], bh[nt]);
            }
    }
}

__device__ __forceinline__ float dot4(float4 a, float4 b) {
    return fmaf(a.x, b.x, fmaf(a.y, b.y, fmaf(a.z, b.z, a.w * b.w)));
}

__global__ void __launch_bounds__(256, 1)
fused_window_attn_mma(const float* __restrict__ x,
                      const float* __restrict__ qkv_w,
                      const float* __restrict__ qkv_b,
                      const float* __restrict__ conv_w,
                      const float* __restrict__ conv_b,
                      float* __restrict__ out)
{
    extern __shared__ char smemc[];
    const uint32_t sb = smem_u32(smemc);
    float* qsF = (float*)(smemc + SM_QS);

    const int t    = threadIdx.x;
    const int wid  = t >> 5;
    const int lane = t & 31;
    const int wi = blockIdx.x;
    const int bz = wi >> 9, by = (wi >> 5) & 15, bx = wi & 31;
    const int z0 = bz * 4, y0 = by * 4, x0 = bx * 4;

    // ---------------- phase 1: gather x -> A hi/lo; load qkv W chunk0 -> B ----
    #pragma unroll
    for (int it = 0; it < 16; ++it) {
        int idx = t + 256 * it;      // 0..4095
        int l  = idx & 63;
        int cp = idx >> 6;           // channel pair 0..63
        int gz = z0 + (l >> 4);
        int gy = y0 + ((l >> 2) & 3);
        int gx = x0 + (l & 3);
        float v0 = 0.f, v1 = 0.f;
        if (gz < D0 && gy < H0 && gx < W0) {
            size_t base = (size_t)(gz * H0 + gy) * W0 + gx;
            v0 = x[(size_t)(2 * cp) * MTOT + base];
            v1 = x[(size_t)(2 * cp + 1) * MTOT + base];
        }
        split_pair(smemc + SM_AHI, smemc + SM_ALO, l, 2 * cp, AST, v0, v1);
    }
    load_wsplit(qkv_w, smemc + SM_BHI, smemc + SM_BLO, t);
    __syncthreads();

    const uint32_t aHi = sb + SM_AHI, aLo = sb + SM_ALO;
    const uint32_t bHi = sb + SM_BHI, bLo = sb + SM_BLO;
    const int n0 = wid * 16;

    // ---------------- phase 2: QKV GEMM, 3 chunks of N=128 ----------------
    #pragma unroll 1
    for (int chunk = 0; chunk < 3; ++chunk) {
        if (chunk > 0) {
            __syncthreads();   // all warps done with previous B
            load_wsplit(qkv_w + chunk * 128 * 128, smemc + SM_BHI, smemc + SM_BLO, t);
            __syncthreads();
        }
        float acc[4][2][4];
        #pragma unroll
        for (int mt = 0; mt < 4; ++mt)
            #pragma unroll
            for (int nt = 0; nt < 2; ++nt)
                #pragma unroll
                for (int e = 0; e < 4; ++e) acc[mt][nt][e] = 0.f;

        mma_block(aHi, aLo, bHi, bLo, lane, n0, acc);

        // epilogue: qs[row][chunk*128 + col] = acc + bias
        #pragma unroll
        for (int mt = 0; mt < 4; ++mt) {
            int row0 = mt * 16 + (lane >> 2);
            #pragma unroll
            for (int nt = 0; nt < 2; ++nt) {
                int col = n0 + nt * 8 + 2 * (lane & 3);
                float2 bv = *(const float2*)(qkv_b + chunk * 128 + col);
                *(float2*)(qsF + (size_t)row0 * QS_STRIDE + chunk * 128 + col) =
                    make_float2(acc[mt][nt][0] + bv.x, acc[mt][nt][1] + bv.y);
                *(float2*)(qsF + (size_t)(row0 + 8) * QS_STRIDE + chunk * 128 + col) =
                    make_float2(acc[mt][nt][2] + bv.x, acc[mt][nt][3] + bv.y);
            }
        }
    }
    __syncthreads();

    // ---------------- phase 3: attention (scalar fp32, warp = head) ----------
    unsigned long long pm = 0ull;
    if (bz == 7 || by == 15 || bx == 31) {
        #pragma unroll
        for (int m = 0; m < 64; ++m) {
            bool p = (bz == 7 && (m >> 4) >= 2) ||
                     (by == 15 && ((m >> 2) & 3) >= 2) ||
                     (bx == 31 && (m & 3) >= 2);
            pm |= (unsigned long long)(p ? 1u : 0u) << m;
        }
    }

    const int head = wid;
    const int r0 = lane, r1 = lane + 32;
    const unsigned p0 = (unsigned)(pm >> r0) & 1u;
    const unsigned p1 = (unsigned)(pm >> r1) & 1u;

    float4 q0[4], q1[4];
    {
        const float4* q0p = (const float4*)(qsF + (size_t)r0 * QS_STRIDE + head * 16);
        const float4* q1p = (const float4*)(qsF + (size_t)r1 * QS_STRIDE + head * 16);
        #pragma unroll
        for (int i = 0; i < 4; ++i) { q0[i] = q0p[i]; q1[i] = q1p[i]; }
    }

    float4 a0[4], a1[4];
    #pragma unroll
    for (int i = 0; i < 4; ++i) {
        a0[i] = make_float4(0.f, 0.f, 0.f, 0.f);
        a1[i] = make_float4(0.f, 0.f, 0.f, 0.f);
    }
    float sum0 = 0.f, sum1 = 0.f;
    const float* kbase = qsF + 128 + head * 16;
    const float* vbase = qsF + 256 + head * 16;

    #pragma unroll 2
    for (int m = 0; m < 64; ++m) {
        const float4* kp = (const float4*)(kbase + (size_t)m * QS_STRIDE);
        float4 k0 = kp[0], k1 = kp[1], k2 = kp[2], k3 = kp[3];
        float s0 = dot4(q0[0], k0) + dot4(q0[1], k1) + dot4(q0[2], k2) + dot4(q0[3], k3);
        float s1 = dot4(q1[0], k0) + dot4(q1[1], k1) + dot4(q1[2], k2) + dot4(q1[3], k3);

        unsigned pmm = (unsigned)(pm >> m) & 1u;
        float e0 = (pmm == p0) ? __expf(s0 * 0.25f) : 0.f;
        float e1 = (pmm == p1) ? __expf(s1 * 0.25f) : 0.f;
        sum0 += e0;
        sum1 += e1;

        const float4* vp = (const float4*)(vbase + (size_t)m * QS_STRIDE);
        float4 v0 = vp[0], v1 = vp[1], v2 = vp[2], v3 = vp[3];
        a0[0].x = fmaf(e0, v0.x, a0[0].x); a0[0].y = fmaf(e0, v0.y, a0[0].y);
        a0[0].z = fmaf(e0, v0.z, a0[0].z); a0[0].w = fmaf(e0, v0.w, a0[0].w);
        a0[1].x = fmaf(e0, v1.x, a0[1].x); a0[1].y = fmaf(e0, v1.y, a0[1].y);
        a0[1].z = fmaf(e0, v1.z, a0[1].z); a0[1].w = fmaf(e0, v1.w, a0[1].w);
        a0[2].x = fmaf(e0, v2.x, a0[2].x); a0[2].y = fmaf(e0, v2.y, a0[2].y);
        a0[2].z = fmaf(e0, v2.z, a0[2].z); a0[2].w = fmaf(e0, v2.w, a0[2].w);
        a0[3].x = fmaf(e0, v3.x, a0[3].x); a0[3].y = fmaf(e0, v3.y, a0[3].y);
        a0[3].z = fmaf(e0, v3.z, a0[3].z); a0[3].w = fmaf(e0, v3.w, a0[3].w);
        a1[0].x = fmaf(e1, v0.x, a1[0].x); a1[0].y = fmaf(e1, v0.y, a1[0].y);
        a1[0].z = fmaf(e1, v0.z, a1[0].z); a1[0].w = fmaf(e1, v0.w, a1[0].w);
        a1[1].x = fmaf(e1, v1.x, a1[1].x); a1[1].y = fmaf(e1, v1.y, a1[1].y);
        a1[1].z = fmaf(e1, v1.z, a1[1].z); a1[1].w = fmaf(e1, v1.w, a1[1].w);
        a1[2].x = fmaf(e1, v2.x, a1[2].x); a1[2].y = fmaf(e1, v2.y, a1[2].y);
        a1[2].z = fmaf(e1, v2.z, a1[2].z); a1[2].w = fmaf(e1, v2.w, a1[2].w);
        a1[3].x = fmaf(e1, v3.x, a1[3].x); a1[3].y = fmaf(e1, v3.y, a1[3].y);
        a1[3].z = fmaf(e1, v3.z, a1[3].z); a1[3].w = fmaf(e1, v3.w, a1[3].w);
    }
    const float inv0 = 1.0f / sum0;
    const float inv1 = 1.0f / sum1;

    __syncthreads();   // everyone done reading qs and done with QKV A/B tiles

    // ---- store Y (hi/lo) into A bufs; load conv W into B bufs ----
    #pragma unroll
    for (int j = 0; j < 4; ++j) {
        int c = head * 16 + 4 * j;
        split_pair(smemc + SM_AHI, smemc + SM_ALO, r0, c,     AST, a0[j].x * inv0, a0[j].y * inv0);
        split_pair(smemc + SM_AHI, smemc + SM_ALO, r0, c + 2, AST, a0[j].z * inv0, a0[j].w * inv0);
        split_pair(smemc + SM_AHI, smemc + SM_ALO, r1, c,     AST, a1[j].x * inv1, a1[j].y * inv1);
        split_pair(smemc + SM_AHI, smemc + SM_ALO, r1, c + 2, AST, a1[j].z * inv1, a1[j].w * inv1);
    }
    load_wsplit(conv_w, smemc + SM_BHI, smemc + SM_BLO, t);
    __syncthreads();

    // ---------------- phase 4: conv GEMM (64 vox x 128 out ch) ---------------
    float cacc[4][2][4];
    #pragma unroll
    for (int mt = 0; mt < 4; ++mt)
        #pragma unroll
        for (int nt = 0; nt < 2; ++nt)
            #pragma unroll
            for (int e = 0; e < 4; ++e) cacc[mt][nt][e] = 0.f;

    mma_block(aHi, aLo, bHi, bLo, lane, n0, cacc);

    #pragma unroll
    for (int mt = 0; mt < 4; ++mt) {
        int m0 = mt * 16 + (lane >> 2);
        int m1 = m0 + 8;
        int gz0 = z0 + (m0 >> 4), gy0 = y0 + ((m0 >> 2) & 3), gx0 = x0 + (m0 & 3);
        int gz1 = z0 + (m1 >> 4), gy1 = y0 + ((m1 >> 2) & 3), gx1 = x0 + (m1 & 3);
        bool ok0 = (gz0 < D0 && gy0 < H0 && gx0 < W0);
        bool ok1 = (gz1 < D0 && gy1 < H0 && gx1 < W0);
        size_t va0 = (size_t)(gz0 * H0 + gy0) * W0 + gx0;
        size_t va1 = (size_t)(gz1 * H0 + gy1) * W0 + gx1;
        #pragma unroll
        for (int nt = 0; nt < 2; ++nt) {
            int o = n0 + nt * 8 + 2 * (lane & 3);
            float2 cb = *(const float2*)(conv_b + o);
            if (ok0) {
                out[(size_t)o * MTOT + va0]       = cacc[mt][nt][0] + cb.x;
                out[(size_t)(o + 1) * MTOT + va0] = cacc[mt][nt][1] + cb.y;
            }
            if (ok1) {
                out[(size_t)o * MTOT + va1]       = cacc[mt][nt][2] + cb.x;
                out[(size_t)(o + 1) * MTOT + va1] = cacc[mt][nt][3] + cb.y;
            }
        }
    }
}

extern "C" void kernel_launch(void* const* d_in, const int* in_sizes, int n_in,
                              void* d_out, int out_size)
{
    const float* x      = (const float*)d_in[0];
    const float* qkv_w  = (const float*)d_in[1];
    const float* qkv_b  = (const float*)d_in[2];
    const float* conv_w = (const float*)d_in[3];
    const float* conv_b = (const float*)d_in[4];
    float* out = (float*)d_out;

    cudaFuncSetAttribute(fused_window_attn_mma,
                         cudaFuncAttributeMaxDynamicSharedMemorySize, SMEM_BYTES);

    fused_window_attn_mma<<<4096, 256, SMEM_BYTES>>>(
        x, qkv_w, qkv_b, conv_w, conv_b, out);
}